// round 12
// baseline (speedup 1.0000x reference)
#include <cuda_runtime.h>
#include <cstdint>

// ---- static config ----
#define BB      16
#define AA      3
#define NC      80
#define WH      76
#define MM      32
#define EE      85                       // 5 + NC
#define CELLS   (WH * WH)                // 5776
#define CPI     (AA * CELLS)             // cells per image: 17328
#define EPI     (CPI * EE)               // elems per image: 1472880
#define NTOT    (BB * EPI)               // 23,566,080 decoded elements
#define NV4     (NTOT / 4)               // 5,891,520 float4s
#define NCH     16
#define QQ      (NV4 / NCH)              // 368,220 (divisible by 85: 85*4332)
#define NCELLS  (BB * CPI)               // 277,248
#define NOOBJ_OFF  NTOT
#define OBJ_OFF    (NTOT + NCELLS)

#define NB_CELL_PER_IMG ((CPI + 255) / 256)        // 68
#define NB_CELL         (NB_CELL_PER_IMG * BB)     // 1088
#define NB_SIG          ((QQ + 255) / 256)         // 1439
#define NB_TOTAL        (NB_CELL + NB_SIG)

__constant__ float c_anchor_w[3] = {10.f / 8.f, 16.f / 8.f, 33.f / 8.f};  // aw/INPUTW*W
__constant__ float c_anchor_h[3] = {13.f / 8.f, 30.f / 8.f, 23.f / 8.f};
__constant__ float c_all_anchors[9][2] = {
    {10.f, 13.f}, {16.f, 30.f}, {33.f, 23.f},
    {30.f, 61.f}, {62.f, 45.f}, {59.f, 119.f},
    {116.f, 90.f}, {156.f, 198.f}, {373.f, 326.f}};

// 3-instruction sigmoid via MUFU.TANH: sigma(x) = 0.5 + 0.5*tanh(x/2)
__device__ __forceinline__ float sigt(float x) {
    float t;
    float h = 0.5f * x;
    asm("tanh.approx.f32 %0, %1;" : "=f"(t) : "f"(h));
    return fmaf(0.5f, t, 0.5f);
}

__device__ __forceinline__ float4 sig4(float4 x) {
    float4 v;
    v.x = sigt(x.x); v.y = sigt(x.y); v.z = sigt(x.z); v.w = sigt(x.w);
    return v;
}

// ------------------------------------------------------------------
// ONE kernel, two block families with DISJOINT write sets:
//  * blocks [NB_CELL, NB_TOTAL): decode stream, 16 float4s per thread at
//    offsets {t + k*QQ}. QQ % 85 == 0, so all chunks share q = t % 85 and
//    ONE `special` predicate. Special float4s (overlapping box lanes e<4)
//    are NOT stored here. Streaming cache hints (read-once/write-once).
//  * blocks [0, NB_CELL): per-cell work — writes the special float4s
//    + noobj + obj.
// Special float4 positions within an 85-float4 period: {0,21,22,42,43,63,64}.
// ------------------------------------------------------------------
__global__ void __launch_bounds__(256) yolo_fused_kernel(
    const float* __restrict__ pred,
    const float* __restrict__ gt,
    float* __restrict__ out) {

    if (blockIdx.x >= NB_CELL) {
        // ---------------- decode stream (MLP=16, streaming) ----------------
        int t = (blockIdx.x - NB_CELL) * blockDim.x + threadIdx.x;
        if (t >= QQ) return;
        const float4* p4 = (const float4*)pred;
        float4* o4 = (float4*)out;

        float4 x[NCH];
#pragma unroll
        for (int k = 0; k < NCH; k++)
            x[k] = __ldcs(&p4[t + k * QQ]);     // 16 independent loads in flight

        int q = t % 85;                          // shared by all chunks
        bool keep = !((q == 0) | (q == 21) | (q == 22) | (q == 42) |
                      (q == 43) | (q == 63) | (q == 64));
#pragma unroll
        for (int k = 0; k < NCH; k++) {
            float4 v = sig4(x[k]);
            if (keep) __stcs(&o4[t + k * QQ], v);
        }
        return;
    }

    // ---------------- cell path ----------------
    __shared__ float4   gbox[MM];     // GT xyxy (pixel)
    __shared__ float    gA[MM];       // GT area
    __shared__ unsigned objbits[8];   // per-block obj bitmap (256 cells)

    int b     = blockIdx.x / NB_CELL_PER_IMG;
    int cblk  = blockIdx.x - b * NB_CELL_PER_IMG;
    int tid   = threadIdx.x;
    int cbase = cblk * 256;

    if (tid < 8) objbits[tid] = 0u;   // warp 0: program-ordered before atomicOr below

    if (tid < MM) {
        const float* g = gt + (size_t)(b * MM + tid) * 6;
        float cx = g[1], cy = g[2], gw = g[3], gh = g[4];
        float x1 = (cx - gw * 0.5f) * 608.0f;
        float y1 = (cy - gh * 0.5f) * 608.0f;
        float x2 = (cx + gw * 0.5f) * 608.0f;
        float y2 = (cy + gh * 0.5f) * 608.0f;
        gbox[tid] = make_float4(x1, y1, x2, y2);
        float garea = (x2 - x1) * (y2 - y1);
        gA[tid] = garea;

        // best-anchor per GT (strict >: first max wins)
        int   best  = 0;
        float bestv = -1.0f;
#pragma unroll
        for (int k = 0; k < 9; k++) {
            float ow = c_all_anchors[k][0] / 608.0f;
            float oh = c_all_anchors[k][1] / 608.0f;
            float ax1 = (cx - ow * 0.5f) * 608.0f;
            float ay1 = (cy - oh * 0.5f) * 608.0f;
            float ax2 = (cx + ow * 0.5f) * 608.0f;
            float ay2 = (cy + oh * 0.5f) * 608.0f;
            float aar = (ax2 - ax1) * (ay2 - ay1);
            float ix = fmaxf(fminf(x2, ax2) - fmaxf(x1, ax1), 0.0f);
            float iy = fmaxf(fminf(y2, ay2) - fmaxf(y1, ay1), 0.0f);
            float inter = ix * iy;
            float iou = inter / (garea + aar - inter);
            if (iou > bestv) { bestv = iou; best = k; }
        }
        if (best < AA) {
            int gi = (int)(cx * (float)WH);
            int gj = (int)(cy * (float)WH);
            int fl = (best * WH + gi) * WH + gj;        // within-image flat cell
            int d  = fl - cbase;
            if (d >= 0 && d < 256)
                atomicOr(&objbits[d >> 5], 1u << (d & 31));
        }
    }
    __syncthreads();

    int c = cbase + tid;
    if (c >= CPI) return;

    int gc  = b * CPI + c;                 // global cell (b*CPI ≡ 0 mod 4)
    int e0  = gc * EE;                     // element index of box lane 0
    int r   = e0 & 3;
    int lo4 = (e0 - r) >> 2;               // aligned float4 index
    const float4* p4 = (const float4*)pred;
    float4* o4 = (float4*)out;

    float buf[8];
    float4 f0 = p4[lo4];
    buf[0] = f0.x; buf[1] = f0.y; buf[2] = f0.z; buf[3] = f0.w;
    if (r) {
        float4 f1 = p4[lo4 + 1];
        buf[4] = f1.x; buf[5] = f1.y; buf[6] = f1.z; buf[7] = f1.w;
    }

    float p0 = buf[r + 0];
    float p1 = buf[r + 1];
    float p2 = buf[r + 2];
    float p3 = buf[r + 3];

    int a  = c / CELLS;
    int sp = c - a * CELLS;
    int w  = sp / WH;
    int h  = sp - w * WH;

    float px = sigt(p0) + (float)h;
    float py = sigt(p1) + (float)w;
    float pw = __expf(p2) * c_anchor_w[a];
    float ph = __expf(p3) * c_anchor_h[a];

    // ---- write the special float4s (box lanes + neighbor sigmoid lanes) ----
    float box[4] = {px, py, pw, ph};
    float obuf[8];
#pragma unroll
    for (int j = 0; j < 8; j++) {
        int rel = j - r;
        float s = sigt(buf[j]);
        obuf[j] = (rel >= 0 && rel < 4) ? box[rel & 3] : s;
    }
    o4[lo4] = make_float4(obuf[0], obuf[1], obuf[2], obuf[3]);
    if (r) o4[lo4 + 1] = make_float4(obuf[4], obuf[5], obuf[6], obuf[7]);

    // ---- noobj / obj (division-free threshold) ----
    float x1 = (px - pw * 0.5f) * 8.0f;
    float y1 = (py - ph * 0.5f) * 8.0f;
    float x2 = (px + pw * 0.5f) * 8.0f;
    float y2 = (py + ph * 0.5f) * 8.0f;
    float pa = (x2 - x1) * (y2 - y1);

    // max(iou) > 0.5  <=>  exists m: 3*inter > pa + gar
    bool anyhi = false;
#pragma unroll 8
    for (int m = 0; m < MM; m++) {
        float4 gb = gbox[m];
        float ix = fmaxf(fminf(x2, gb.z) - fmaxf(x1, gb.x), 0.0f);
        float iy = fmaxf(fminf(y2, gb.w) - fmaxf(y1, gb.y), 0.0f);
        float inter = ix * iy;
        anyhi |= (3.0f * inter > pa + gA[m]);
    }

    bool isobj = (objbits[tid >> 5] >> (tid & 31)) & 1u;
    out[OBJ_OFF + gc]   = isobj ? 1.0f : 0.0f;
    out[NOOBJ_OFF + gc] = (!anyhi && !isobj) ? 1.0f : 0.0f;
}

extern "C" void kernel_launch(void* const* d_in, const int* in_sizes, int n_in,
                              void* d_out, int out_size) {
    const float* pred = (const float*)d_in[0];
    const float* gt   = (const float*)d_in[1];
    float* out = (float*)d_out;

    (void)in_sizes; (void)n_in; (void)out_size;

    yolo_fused_kernel<<<NB_TOTAL, 256>>>(pred, gt, out);
}

// round 13
// speedup vs baseline: 1.1171x; 1.1171x over previous
#include <cuda_runtime.h>
#include <cstdint>

// ---- static config ----
#define BB      16
#define AA      3
#define NC      80
#define WH      76
#define MM      32
#define EE      85                       // 5 + NC
#define CELLS   (WH * WH)                // 5776
#define CPI     (AA * CELLS)             // cells per image: 17328
#define EPI     (CPI * EE)               // elems per image: 1472880
#define NTOT    (BB * EPI)               // 23,566,080 decoded elements
#define NV4     (NTOT / 4)               // 5,891,520 float4s
#define NCH     8
#define QQ      (NV4 / NCH)              // 736,440 = 85 * 8664
#define NCELLS  (BB * CPI)               // 277,248
#define NOOBJ_OFF  NTOT
#define OBJ_OFF    (NTOT + NCELLS)

#define NB_CELL_PER_IMG ((CPI + 255) / 256)        // 68
#define NB_CELL         (NB_CELL_PER_IMG * BB)     // 1088
#define NB_SIG          ((QQ + 255) / 256)         // 2877
#define NB_TOTAL        (NB_CELL + NB_SIG)

__constant__ float c_anchor_w[3] = {10.f / 8.f, 16.f / 8.f, 33.f / 8.f};  // aw/INPUTW*W
__constant__ float c_anchor_h[3] = {13.f / 8.f, 30.f / 8.f, 23.f / 8.f};
__constant__ float c_all_anchors[9][2] = {
    {10.f, 13.f}, {16.f, 30.f}, {33.f, 23.f},
    {30.f, 61.f}, {62.f, 45.f}, {59.f, 119.f},
    {116.f, 90.f}, {156.f, 198.f}, {373.f, 326.f}};

// 3-instruction sigmoid via MUFU.TANH: sigma(x) = 0.5 + 0.5*tanh(x/2)
__device__ __forceinline__ float sigt(float x) {
    float t;
    float h = 0.5f * x;
    asm("tanh.approx.f32 %0, %1;" : "=f"(t) : "f"(h));
    return fmaf(0.5f, t, 0.5f);
}

__device__ __forceinline__ float4 sig4(float4 x) {
    float4 v;
    v.x = sigt(x.x); v.y = sigt(x.y); v.z = sigt(x.z); v.w = sigt(x.w);
    return v;
}

// ------------------------------------------------------------------
// ONE kernel, two block families with DISJOINT write sets:
//  * blocks [NB_CELL, NB_TOTAL): decode stream. Thread t = 85*g + q
//    handles the 8 float4s at index g*680 + 85*k + q (k = 0..7).
//    All 8 chunks share q -> ONE `special` predicate, and the chunk
//    stride (85 float4s = 1360 B) fits the LDG/STG immediate-offset
//    field -> single base address, 8 imm-offset loads + stores.
//    Special float4s (overlapping box lanes e<4) are NOT stored here.
//  * blocks [0, NB_CELL): per-cell work — writes the special float4s
//    + noobj + obj.
// Special float4 positions within an 85-float4 period: {0,21,22,42,43,63,64}.
// ------------------------------------------------------------------
__global__ void __launch_bounds__(256) yolo_fused_kernel(
    const float* __restrict__ pred,
    const float* __restrict__ gt,
    float* __restrict__ out) {

    if (blockIdx.x >= NB_CELL) {
        // ---------------- decode stream (MLP=8, imm-offset addressing) ----------------
        int t = (blockIdx.x - NB_CELL) * blockDim.x + threadIdx.x;
        if (t >= QQ) return;

        int g = t / 85;                 // magic-mul
        int q = t - g * 85;
        int f = g * 680 + q;            // base float4 index (fits int)

        const float4* pb = (const float4*)pred + f;
        float4*       ob = (float4*)out + f;

        float4 x[NCH];
#pragma unroll
        for (int k = 0; k < NCH; k++)
            x[k] = __ldcs(pb + 85 * k);          // imm offsets, 8 in flight

        bool keep = !((q == 0) | (q == 21) | (q == 22) | (q == 42) |
                      (q == 43) | (q == 63) | (q == 64));
#pragma unroll
        for (int k = 0; k < NCH; k++) {
            float4 v = sig4(x[k]);
            if (keep) __stcs(ob + 85 * k, v);
        }
        return;
    }

    // ---------------- cell path ----------------
    __shared__ float4   gbox[MM];     // GT xyxy (pixel)
    __shared__ float    gA[MM];       // GT area
    __shared__ unsigned objbits[8];   // per-block obj bitmap (256 cells)

    int b     = blockIdx.x / NB_CELL_PER_IMG;
    int cblk  = blockIdx.x - b * NB_CELL_PER_IMG;
    int tid   = threadIdx.x;
    int cbase = cblk * 256;

    if (tid < 8) objbits[tid] = 0u;   // warp 0: program-ordered before atomicOr below

    if (tid < MM) {
        const float* g = gt + (size_t)(b * MM + tid) * 6;
        float cx = g[1], cy = g[2], gw = g[3], gh = g[4];
        float x1 = (cx - gw * 0.5f) * 608.0f;
        float y1 = (cy - gh * 0.5f) * 608.0f;
        float x2 = (cx + gw * 0.5f) * 608.0f;
        float y2 = (cy + gh * 0.5f) * 608.0f;
        gbox[tid] = make_float4(x1, y1, x2, y2);
        float garea = (x2 - x1) * (y2 - y1);
        gA[tid] = garea;

        // best-anchor per GT (strict >: first max wins)
        int   best  = 0;
        float bestv = -1.0f;
#pragma unroll
        for (int k = 0; k < 9; k++) {
            float ow = c_all_anchors[k][0] / 608.0f;
            float oh = c_all_anchors[k][1] / 608.0f;
            float ax1 = (cx - ow * 0.5f) * 608.0f;
            float ay1 = (cy - oh * 0.5f) * 608.0f;
            float ax2 = (cx + ow * 0.5f) * 608.0f;
            float ay2 = (cy + oh * 0.5f) * 608.0f;
            float aar = (ax2 - ax1) * (ay2 - ay1);
            float ix = fmaxf(fminf(x2, ax2) - fmaxf(x1, ax1), 0.0f);
            float iy = fmaxf(fminf(y2, ay2) - fmaxf(y1, ay1), 0.0f);
            float inter = ix * iy;
            float iou = inter / (garea + aar - inter);
            if (iou > bestv) { bestv = iou; best = k; }
        }
        if (best < AA) {
            int gi = (int)(cx * (float)WH);
            int gj = (int)(cy * (float)WH);
            int fl = (best * WH + gi) * WH + gj;        // within-image flat cell
            int d  = fl - cbase;
            if (d >= 0 && d < 256)
                atomicOr(&objbits[d >> 5], 1u << (d & 31));
        }
    }
    __syncthreads();

    int c = cbase + tid;
    if (c >= CPI) return;

    int gc  = b * CPI + c;                 // global cell (b*CPI ≡ 0 mod 4)
    int e0  = gc * EE;                     // element index of box lane 0
    int r   = e0 & 3;
    int lo4 = (e0 - r) >> 2;               // aligned float4 index
    const float4* p4 = (const float4*)pred;
    float4* o4 = (float4*)out;

    float buf[8];
    float4 f0 = p4[lo4];
    buf[0] = f0.x; buf[1] = f0.y; buf[2] = f0.z; buf[3] = f0.w;
    if (r) {
        float4 f1 = p4[lo4 + 1];
        buf[4] = f1.x; buf[5] = f1.y; buf[6] = f1.z; buf[7] = f1.w;
    }

    float p0 = buf[r + 0];
    float p1 = buf[r + 1];
    float p2 = buf[r + 2];
    float p3 = buf[r + 3];

    int a  = c / CELLS;
    int sp = c - a * CELLS;
    int w  = sp / WH;
    int h  = sp - w * WH;

    float px = sigt(p0) + (float)h;
    float py = sigt(p1) + (float)w;
    float pw = __expf(p2) * c_anchor_w[a];
    float ph = __expf(p3) * c_anchor_h[a];

    // ---- write the special float4s (box lanes + neighbor sigmoid lanes) ----
    float box[4] = {px, py, pw, ph};
    float obuf[8];
#pragma unroll
    for (int j = 0; j < 8; j++) {
        int rel = j - r;
        float s = sigt(buf[j]);
        obuf[j] = (rel >= 0 && rel < 4) ? box[rel & 3] : s;
    }
    o4[lo4] = make_float4(obuf[0], obuf[1], obuf[2], obuf[3]);
    if (r) o4[lo4 + 1] = make_float4(obuf[4], obuf[5], obuf[6], obuf[7]);

    // ---- noobj / obj (division-free threshold) ----
    float x1 = (px - pw * 0.5f) * 8.0f;
    float y1 = (py - ph * 0.5f) * 8.0f;
    float x2 = (px + pw * 0.5f) * 8.0f;
    float y2 = (py + ph * 0.5f) * 8.0f;
    float pa = (x2 - x1) * (y2 - y1);

    // max(iou) > 0.5  <=>  exists m: 3*inter > pa + gar
    bool anyhi = false;
#pragma unroll 8
    for (int m = 0; m < MM; m++) {
        float4 gb = gbox[m];
        float ix = fmaxf(fminf(x2, gb.z) - fmaxf(x1, gb.x), 0.0f);
        float iy = fmaxf(fminf(y2, gb.w) - fmaxf(y1, gb.y), 0.0f);
        float inter = ix * iy;
        anyhi |= (3.0f * inter > pa + gA[m]);
    }

    bool isobj = (objbits[tid >> 5] >> (tid & 31)) & 1u;
    out[OBJ_OFF + gc]   = isobj ? 1.0f : 0.0f;
    out[NOOBJ_OFF + gc] = (!anyhi && !isobj) ? 1.0f : 0.0f;
}

extern "C" void kernel_launch(void* const* d_in, const int* in_sizes, int n_in,
                              void* d_out, int out_size) {
    const float* pred = (const float*)d_in[0];
    const float* gt   = (const float*)d_in[1];
    float* out = (float*)d_out;

    (void)in_sizes; (void)n_in; (void)out_size;

    yolo_fused_kernel<<<NB_TOTAL, 256>>>(pred, gt, out);
}

// round 14
// speedup vs baseline: 1.2397x; 1.1097x over previous
#include <cuda_runtime.h>
#include <cstdint>

// ---- static config ----
#define BB      16
#define AA      3
#define NC      80
#define WH      76
#define MM      32
#define EE      85                       // 5 + NC
#define CELLS   (WH * WH)                // 5776
#define CPI     (AA * CELLS)             // cells per image: 17328
#define EPI     (CPI * EE)               // elems per image: 1472880
#define NTOT    (BB * EPI)               // 23,566,080 decoded elements
#define NV4     (NTOT / 4)               // 5,891,520 float4s
#define NCH     8
#define QQ      (NV4 / NCH)              // 736,440 = 85 * 8664
#define NCELLS  (BB * CPI)               // 277,248
#define NOOBJ_OFF  NTOT
#define OBJ_OFF    (NTOT + NCELLS)

#define NB_CELL_PER_IMG ((CPI + 255) / 256)        // 68
#define NB_CELL         (NB_CELL_PER_IMG * BB)     // 1088
#define NB_SIG          ((QQ + 255) / 256)         // 2877
#define NB_TOTAL        (NB_CELL + NB_SIG)         // 3965

__constant__ float c_anchor_w[3] = {10.f / 8.f, 16.f / 8.f, 33.f / 8.f};  // aw/INPUTW*W
__constant__ float c_anchor_h[3] = {13.f / 8.f, 30.f / 8.f, 23.f / 8.f};
__constant__ float c_all_anchors[9][2] = {
    {10.f, 13.f}, {16.f, 30.f}, {33.f, 23.f},
    {30.f, 61.f}, {62.f, 45.f}, {59.f, 119.f},
    {116.f, 90.f}, {156.f, 198.f}, {373.f, 326.f}};

// 3-instruction sigmoid via MUFU.TANH: sigma(x) = 0.5 + 0.5*tanh(x/2)
__device__ __forceinline__ float sigt(float x) {
    float t;
    float h = 0.5f * x;
    asm("tanh.approx.f32 %0, %1;" : "=f"(t) : "f"(h));
    return fmaf(0.5f, t, 0.5f);
}

__device__ __forceinline__ float4 sig4(float4 x) {
    float4 v;
    v.x = sigt(x.x); v.y = sigt(x.y); v.z = sigt(x.z); v.w = sigt(x.w);
    return v;
}

// ------------------------------------------------------------------
// ONE kernel, two INTERLEAVED block families with DISJOINT write sets:
//  * cell blocks: every 3rd blockIdx while i/3 < NB_CELL — per-cell work,
//    writes the "special" float4s (those overlapping box lanes e<4) +
//    noobj + obj. Interleaving spreads their ALU-heavy work across all
//    SMs so it hides under the decode blocks' memory stalls.
//  * decode blocks: the rest — thread t = 85*g + q handles the 8 float4s
//    at g*680 + 85*k + q (k=0..7); all chunks share q -> ONE `special`
//    predicate; 1360B chunk stride fits LDG/STG immediate offsets.
// Special float4 positions within an 85-float4 period: {0,21,22,42,43,63,64}.
// ------------------------------------------------------------------
__global__ void __launch_bounds__(256) yolo_fused_kernel(
    const float* __restrict__ pred,
    const float* __restrict__ gt,
    float* __restrict__ out) {

    int i = blockIdx.x;
    bool iscell = ((i % 3) == 0) && (i / 3 < NB_CELL);

    if (!iscell) {
        // ---------------- decode stream (MLP=8, imm-offset addressing) ----------------
        int nc_before = (i + 2) / 3;                  // cell blocks with index < i
        if (nc_before > NB_CELL) nc_before = NB_CELL;
        int t = (i - nc_before) * blockDim.x + threadIdx.x;
        if (t >= QQ) return;

        int g = t / 85;                 // magic-mul
        int q = t - g * 85;
        int f = g * 680 + q;            // base float4 index

        const float4* pb = (const float4*)pred + f;
        float4*       ob = (float4*)out + f;

        float4 x[NCH];
#pragma unroll
        for (int k = 0; k < NCH; k++)
            x[k] = __ldcs(pb + 85 * k);          // imm offsets, 8 in flight

        bool keep = !((q == 0) | (q == 21) | (q == 22) | (q == 42) |
                      (q == 43) | (q == 63) | (q == 64));
#pragma unroll
        for (int k = 0; k < NCH; k++) {
            float4 v = sig4(x[k]);
            if (keep) __stcs(ob + 85 * k, v);
        }
        return;
    }

    // ---------------- cell path ----------------
    __shared__ float4   gbox[MM];     // GT xyxy (pixel)
    __shared__ float    gA[MM];       // GT area
    __shared__ unsigned objbits[8];   // per-block obj bitmap (256 cells)

    int cid   = i / 3;                // 0 .. NB_CELL-1
    int b     = cid / NB_CELL_PER_IMG;
    int cblk  = cid - b * NB_CELL_PER_IMG;
    int tid   = threadIdx.x;
    int cbase = cblk * 256;

    if (tid < 8) objbits[tid] = 0u;   // warp 0: program-ordered before atomicOr below

    if (tid < MM) {
        const float* g = gt + (size_t)(b * MM + tid) * 6;
        float cx = g[1], cy = g[2], gw = g[3], gh = g[4];
        float x1 = (cx - gw * 0.5f) * 608.0f;
        float y1 = (cy - gh * 0.5f) * 608.0f;
        float x2 = (cx + gw * 0.5f) * 608.0f;
        float y2 = (cy + gh * 0.5f) * 608.0f;
        gbox[tid] = make_float4(x1, y1, x2, y2);
        float garea = (x2 - x1) * (y2 - y1);
        gA[tid] = garea;

        // best-anchor per GT (strict >: first max wins)
        int   best  = 0;
        float bestv = -1.0f;
#pragma unroll
        for (int k = 0; k < 9; k++) {
            float ow = c_all_anchors[k][0] / 608.0f;
            float oh = c_all_anchors[k][1] / 608.0f;
            float ax1 = (cx - ow * 0.5f) * 608.0f;
            float ay1 = (cy - oh * 0.5f) * 608.0f;
            float ax2 = (cx + ow * 0.5f) * 608.0f;
            float ay2 = (cy + oh * 0.5f) * 608.0f;
            float aar = (ax2 - ax1) * (ay2 - ay1);
            float ix = fmaxf(fminf(x2, ax2) - fmaxf(x1, ax1), 0.0f);
            float iy = fmaxf(fminf(y2, ay2) - fmaxf(y1, ay1), 0.0f);
            float inter = ix * iy;
            float iou = inter / (garea + aar - inter);
            if (iou > bestv) { bestv = iou; best = k; }
        }
        if (best < AA) {
            int gi = (int)(cx * (float)WH);
            int gj = (int)(cy * (float)WH);
            int fl = (best * WH + gi) * WH + gj;        // within-image flat cell
            int d  = fl - cbase;
            if (d >= 0 && d < 256)
                atomicOr(&objbits[d >> 5], 1u << (d & 31));
        }
    }
    __syncthreads();

    int c = cbase + tid;
    if (c >= CPI) return;

    int gc  = b * CPI + c;                 // global cell (b*CPI ≡ 0 mod 4)
    int e0  = gc * EE;                     // element index of box lane 0
    int r   = e0 & 3;
    int lo4 = (e0 - r) >> 2;               // aligned float4 index
    const float4* p4 = (const float4*)pred;
    float4* o4 = (float4*)out;

    float buf[8];
    float4 f0 = p4[lo4];
    buf[0] = f0.x; buf[1] = f0.y; buf[2] = f0.z; buf[3] = f0.w;
    if (r) {
        float4 f1 = p4[lo4 + 1];
        buf[4] = f1.x; buf[5] = f1.y; buf[6] = f1.z; buf[7] = f1.w;
    }

    float p0 = buf[r + 0];
    float p1 = buf[r + 1];
    float p2 = buf[r + 2];
    float p3 = buf[r + 3];

    int a  = c / CELLS;
    int sp = c - a * CELLS;
    int w  = sp / WH;
    int h  = sp - w * WH;

    float px = sigt(p0) + (float)h;
    float py = sigt(p1) + (float)w;
    float pw = __expf(p2) * c_anchor_w[a];
    float ph = __expf(p3) * c_anchor_h[a];

    // ---- write the special float4s (box lanes + neighbor sigmoid lanes) ----
    float box[4] = {px, py, pw, ph};
    float obuf[8];
#pragma unroll
    for (int j = 0; j < 8; j++) {
        int rel = j - r;
        float s = sigt(buf[j]);
        obuf[j] = (rel >= 0 && rel < 4) ? box[rel & 3] : s;
    }
    o4[lo4] = make_float4(obuf[0], obuf[1], obuf[2], obuf[3]);
    if (r) o4[lo4 + 1] = make_float4(obuf[4], obuf[5], obuf[6], obuf[7]);

    // ---- noobj / obj (division-free threshold) ----
    float x1 = (px - pw * 0.5f) * 8.0f;
    float y1 = (py - ph * 0.5f) * 8.0f;
    float x2 = (px + pw * 0.5f) * 8.0f;
    float y2 = (py + ph * 0.5f) * 8.0f;
    float pa = (x2 - x1) * (y2 - y1);

    // max(iou) > 0.5  <=>  exists m: 3*inter > pa + gar
    bool anyhi = false;
#pragma unroll 8
    for (int m = 0; m < MM; m++) {
        float4 gb = gbox[m];
        float ix = fmaxf(fminf(x2, gb.z) - fmaxf(x1, gb.x), 0.0f);
        float iy = fmaxf(fminf(y2, gb.w) - fmaxf(y1, gb.y), 0.0f);
        float inter = ix * iy;
        anyhi |= (3.0f * inter > pa + gA[m]);
    }

    bool isobj = (objbits[tid >> 5] >> (tid & 31)) & 1u;
    out[OBJ_OFF + gc]   = isobj ? 1.0f : 0.0f;
    out[NOOBJ_OFF + gc] = (!anyhi && !isobj) ? 1.0f : 0.0f;
}

extern "C" void kernel_launch(void* const* d_in, const int* in_sizes, int n_in,
                              void* d_out, int out_size) {
    const float* pred = (const float*)d_in[0];
    const float* gt   = (const float*)d_in[1];
    float* out = (float*)d_out;

    (void)in_sizes; (void)n_in; (void)out_size;

    yolo_fused_kernel<<<NB_TOTAL, 256>>>(pred, gt, out);
}